// round 3
// baseline (speedup 1.0000x reference)
#include <cuda_runtime.h>

// RiRoIAlign for GB300 — smem-tiled gather.
// features: (B=2, Ctot=256, H=256, W=256) fp32
// rois: (512, 6) fp32 = [batch, cx, cy, w, h, theta]
// out: (512, 256, 7, 7) fp32, channel = c*8 + o  (C=32, O=8)
//
// Per (roi, channel, plane): load the rotated-ROI bounding box of the feature
// plane into smem (coalesced), then bilinear-sample 196 points from smem.
// Samples are bin-major (4 per bin) and reduced with quad shuffles.

#define HH 256
#define WW 256
#define CT 256
#define OO 8
#define NBIN 49
#define NS 196
#define HW (HH * WW)
#define TILE_ELEMS 8190   // 90*91 safety margin; worst case needs <= 87*89

__global__ __launch_bounds__(256, 5)
void riroi_kernel(const float* __restrict__ features,
                  const float* __restrict__ rois,
                  float* __restrict__ out)
{
    __shared__ float  tile[TILE_ELEMS];
    __shared__ float4 sw[224];     // bilinear weights (w00,w01,w10,w11) * valid
    __shared__ short4 sxy[224];    // absolute tap coords: x_low, y_low, x_high, y_high
    __shared__ float  acc[OO * NBIN];
    __shared__ int    sbb[4];      // x0, y0, x1, y1

    const int r   = blockIdx.x;
    const int cg  = blockIdx.y;
    const int tid = threadIdx.x;

    const float b_f = rois[r * 6 + 0];
    const float cwv = rois[r * 6 + 1] * 0.125f;
    const float chv = rois[r * 6 + 2] * 0.125f;
    const float rw  = fmaxf(rois[r * 6 + 3] * 0.125f, 1.0f);
    const float rh  = fmaxf(rois[r * 6 + 4] * 0.125f, 1.0f);
    const float th  = rois[r * 6 + 5];
    const int   b   = (int)b_f;

    const float st  = sinf(th);
    const float ctt = cosf(th);

    const float indf   = (th * 8.0f) / 6.283185307179586f;
    const float indflo = floorf(indf);
    const float lv     = indf - indflo;
    const float rv     = 1.0f - lv;
    int ind = (int)indflo;
    ind = ((ind % 8) + 8) % 8;

    const float bin_h = rh / 7.0f;
    const float bin_w = rw / 7.0f;

    if (tid == 0) { sbb[0] = WW; sbb[1] = HH; sbb[2] = 0; sbb[3] = 0; }
    __syncthreads();

    // ---- geometry: sample t = bin*4 + (gy*2+gx) ----
    if (tid < NS) {
        const int t   = tid;
        const int gx  = t & 1;
        const int gy  = (t >> 1) & 1;
        const int bin = t >> 2;
        const int py  = bin / 7;
        const int px  = bin - py * 7;

        const float yy = -rh * 0.5f + ((float)py + ((float)gy + 0.5f) * 0.5f) * bin_h;
        const float xx = -rw * 0.5f + ((float)px + ((float)gx + 0.5f) * 0.5f) * bin_w;

        const float x = xx * ctt - yy * st + cwv;
        const float y = xx * st + yy * ctt + chv;

        const bool valid = (y > -1.0f) && (y < 256.0f) && (x > -1.0f) && (x < 256.0f);

        const float yc = fmaxf(y, 0.0f);
        const float xc = fmaxf(x, 0.0f);
        int yl = (int)yc;
        int xl = (int)xc;
        int yh, xh;
        float yv, xv;
        if (yl >= HH - 1) { yl = HH - 1; yh = HH - 1; yv = (float)(HH - 1); }
        else              { yh = yl + 1;              yv = yc; }
        if (xl >= WW - 1) { xl = WW - 1; xh = WW - 1; xv = (float)(WW - 1); }
        else              { xh = xl + 1;              xv = xc; }

        const float ly = yv - (float)yl;
        const float lx = xv - (float)xl;
        const float hy = 1.0f - ly;
        const float hx = 1.0f - lx;
        const float vm = valid ? 1.0f : 0.0f;

        sw[t]  = make_float4(hy * hx * vm, hy * lx * vm, ly * hx * vm, ly * lx * vm);
        sxy[t] = make_short4((short)xl, (short)yl, (short)xh, (short)yh);

        atomicMin(&sbb[0], xl);
        atomicMin(&sbb[1], yl);
        atomicMax(&sbb[2], xh);
        atomicMax(&sbb[3], yh);
    } else {
        // padding so all lanes can sample safely (value discarded)
        sw[tid < 224 ? tid : 223]  = make_float4(0.f, 0.f, 0.f, 0.f);
    }
    __syncthreads();

    const int x0 = sbb[0];
    const int y0 = sbb[1];
    const int tw = sbb[2] - x0 + 1;
    const int th2 = sbb[3] - y0 + 1;
    const int pitch = tw | 1;            // odd pitch vs bank conflicts

    const int wid  = tid >> 5;
    const int lane = tid & 31;
    const int ts   = (tid < NS) ? tid : (NS - 1);   // safe sample idx for idle lanes

    const float* fb = features + ((size_t)b * CT + (size_t)cg * 8 * OO) * (size_t)HW;

    for (int cc = 0; cc < 8; ++cc) {
        const float* cb = fb + (size_t)cc * OO * HW;

        #pragma unroll 1
        for (int plane = 0; plane < OO; ++plane) {
            const float* pl = cb + plane * HW + (size_t)y0 * WW + x0;

            // coalesced tile load: warp per row stripe
            for (int row = wid; row < th2; row += 8) {
                const float* src = pl + (size_t)row * WW;
                float* dst = tile + row * pitch;
                for (int col = lane; col < tw; col += 32)
                    dst[col] = __ldg(src + col);
            }
            __syncthreads();

            // sample from smem
            const short4 q = sxy[ts];
            const float4 w = sw[ts];
            const int rl = ((int)q.y - y0) * pitch;
            const int rh2 = ((int)q.w - y0) * pitch;
            const int cl = (int)q.x - x0;
            const int ch2 = (int)q.z - x0;

            float v = w.x * tile[rl + cl] + w.y * tile[rl + ch2]
                    + w.z * tile[rh2 + cl] + w.w * tile[rh2 + ch2];

            // quad reduce: 4 samples of one bin sit in consecutive lanes
            v += __shfl_xor_sync(0xFFFFFFFFu, v, 1);
            v += __shfl_xor_sync(0xFFFFFFFFu, v, 2);

            if (tid < NS && (tid & 3) == 0)
                acc[plane * NBIN + (tid >> 2)] = v;
            __syncthreads();
        }

        // orientation mix + coalesced write for channel c = cg*8+cc
        const int c = cg * 8 + cc;
        float* ob = out + ((size_t)r * CT + (size_t)c * OO) * (size_t)NBIN;
        for (int it = tid; it < OO * NBIN; it += 256) {
            const int o   = it / NBIN;
            const int bin = it - o * NBIN;
            const int p0  = (o - ind + 8) & 7;
            const int p1  = (p0 + 1) & 7;
            ob[it] = 0.25f * (rv * acc[p0 * NBIN + bin] + lv * acc[p1 * NBIN + bin]);
        }
        // next iteration's first __syncthreads (after tile load) also guarantees
        // all output reads of acc completed before acc is rewritten; but the tile
        // itself is rewritten before that sync — the trailing sync of the plane
        // loop already ensured all sampling finished. acc, however, is read here
        // and rewritten after the NEXT sync, so this is safe without an extra bar.
        __syncthreads();
    }
}

extern "C" void kernel_launch(void* const* d_in, const int* in_sizes, int n_in,
                              void* d_out, int out_size)
{
    const float* features = (const float*)d_in[0];
    const float* rois     = (const float*)d_in[1];
    float*       out      = (float*)d_out;

    const int R = in_sizes[1] / 6;
    dim3 grid((unsigned)R, 4);
    riroi_kernel<<<grid, 256>>>(features, rois, out);
}

// round 4
// speedup vs baseline: 2.0146x; 2.0146x over previous
#include <cuda_runtime.h>

// RiRoIAlign for GB300 — scattered gather, channel-fused.
// features: (B=2, Ctot=256, H=256, W=256) fp32
// rois: (512, 6) fp32 = [batch, cx, cy, w, h, theta]
// out: (512, 256, 7, 7) fp32, channel = c*8 + o  (C=32, O=8)
//
// Each thread owns one (plane, bin) item and accumulates it for all 8
// channels of its channel group: tap offsets/weights are read from smem once
// and reused 8x (per-channel address delta is the constant 8*HW). 8
// independent accumulator chains give high MLP. Two barriers per CTA total.

#define HH 256
#define WW 256
#define CT 256
#define OO 8
#define NBIN 49
#define NS 196
#define HW (HH * WW)
#define NITEM (OO * NBIN)        // 392
#define NOUT  (8 * NITEM)        // 3136 floats per CTA, contiguous

__global__ __launch_bounds__(256, 4)
void riroi_kernel(const float* __restrict__ features,
                  const float* __restrict__ rois,
                  float* __restrict__ out)
{
    __shared__ int4   soff[NS];          // 4 bilinear tap offsets (y*W+x)
    __shared__ float4 swt[NS];           // 4 bilinear weights (incl. valid)
    __shared__ float  acc[NOUT];         // [cc][plane*49+bin]

    const int r   = blockIdx.x;
    const int cg  = blockIdx.y;
    const int tid = threadIdx.x;

    const float b_f = rois[r * 6 + 0];
    const float cwv = rois[r * 6 + 1] * 0.125f;
    const float chv = rois[r * 6 + 2] * 0.125f;
    const float rw  = fmaxf(rois[r * 6 + 3] * 0.125f, 1.0f);
    const float rh  = fmaxf(rois[r * 6 + 4] * 0.125f, 1.0f);
    const float th  = rois[r * 6 + 5];
    const int   b   = (int)b_f;

    const float st  = sinf(th);
    const float ctt = cosf(th);

    const float indf   = (th * 8.0f) / 6.283185307179586f;
    const float indflo = floorf(indf);
    const float lv     = indf - indflo;
    const float rv     = 1.0f - lv;
    int ind = (int)indflo;
    ind = ((ind % 8) + 8) % 8;

    const float bin_h = rh / 7.0f;
    const float bin_w = rw / 7.0f;

    // ---- geometry: sample s in order (py, gy, px, gx) ----
    if (tid < NS) {
        const int s  = tid;
        const int gx = s & 1;
        const int px = (s >> 1) % 7;
        const int gy = (s / 14) & 1;
        const int py = s / 28;

        const float yy = -rh * 0.5f + ((float)py + ((float)gy + 0.5f) * 0.5f) * bin_h;
        const float xx = -rw * 0.5f + ((float)px + ((float)gx + 0.5f) * 0.5f) * bin_w;

        const float x = xx * ctt - yy * st + cwv;
        const float y = xx * st + yy * ctt + chv;

        const bool valid = (y > -1.0f) && (y < 256.0f) && (x > -1.0f) && (x < 256.0f);

        const float yc = fmaxf(y, 0.0f);
        const float xc = fmaxf(x, 0.0f);
        int yl = (int)yc;
        int xl = (int)xc;
        int yh, xh;
        float yv, xv;
        if (yl >= HH - 1) { yl = HH - 1; yh = HH - 1; yv = (float)(HH - 1); }
        else              { yh = yl + 1;              yv = yc; }
        if (xl >= WW - 1) { xl = WW - 1; xh = WW - 1; xv = (float)(WW - 1); }
        else              { xh = xl + 1;              xv = xc; }

        const float ly = yv - (float)yl;
        const float lx = xv - (float)xl;
        const float hy = 1.0f - ly;
        const float hx = 1.0f - lx;
        const float vm = valid ? 1.0f : 0.0f;

        swt[s]  = make_float4(hy * hx * vm, hy * lx * vm, ly * hx * vm, ly * lx * vm);
        soff[s] = make_int4(yl * WW + xl, yl * WW + xh, yh * WW + xl, yh * WW + xh);
    }
    __syncthreads();

    // base: features[b, cg*64 + cc*8 + plane, :, :]
    const float* fb = features + ((size_t)b * CT + (size_t)cg * 64) * (size_t)HW;

    for (int it = tid; it < NITEM; it += 256) {
        const int plane = it / NBIN;
        const int bin   = it - plane * NBIN;
        const int py    = bin / 7;
        const int px    = bin - py * 7;
        const float* pl = fb + plane * HW;

        float a0 = 0.f, a1 = 0.f, a2 = 0.f, a3 = 0.f;
        float a4 = 0.f, a5 = 0.f, a6 = 0.f, a7 = 0.f;

        #pragma unroll
        for (int gy = 0; gy < 2; ++gy) {
            #pragma unroll
            for (int gx = 0; gx < 2; ++gx) {
                const int s = ((py * 2 + gy) * 7 + px) * 2 + gx;
                const int4   o = soff[s];
                const float4 w = swt[s];
                const float* p = pl;
                #pragma unroll
                for (int cc = 0; cc < 8; ++cc) {
                    const float v = w.x * __ldg(p + o.x) + w.y * __ldg(p + o.y)
                                  + w.z * __ldg(p + o.z) + w.w * __ldg(p + o.w);
                    switch (cc) {
                        case 0: a0 += v; break;  case 1: a1 += v; break;
                        case 2: a2 += v; break;  case 3: a3 += v; break;
                        case 4: a4 += v; break;  case 5: a5 += v; break;
                        case 6: a6 += v; break;  default: a7 += v; break;
                    }
                    p += 8 * HW;
                }
            }
        }
        acc[0 * NITEM + it] = a0;  acc[1 * NITEM + it] = a1;
        acc[2 * NITEM + it] = a2;  acc[3 * NITEM + it] = a3;
        acc[4 * NITEM + it] = a4;  acc[5 * NITEM + it] = a5;
        acc[6 * NITEM + it] = a6;  acc[7 * NITEM + it] = a7;
    }
    __syncthreads();

    // output: out[r, cg*64 .. cg*64+64, 7, 7] is one contiguous 3136-float run;
    // j = cc*392 + o*49 + bin == (cc*8+o)*49 + bin matches channel-major order.
    float* ob = out + ((size_t)r * CT + (size_t)cg * 64) * (size_t)NBIN;
    #pragma unroll
    for (int jj = 0; jj < NOUT / 256; ++jj) {
        const int j    = jj * 256 + tid;
        const int cc   = j / NITEM;
        const int rest = j - cc * NITEM;
        const int o    = rest / NBIN;
        const int bin  = rest - o * NBIN;
        const int p0   = (o - ind + 8) & 7;
        const int p1   = (p0 + 1) & 7;
        ob[j] = 0.25f * (rv * acc[cc * NITEM + p0 * NBIN + bin]
                       + lv * acc[cc * NITEM + p1 * NBIN + bin]);
    }
    // NOUT = 3136 = 12*256 + 64: tail
    {
        const int j = 12 * 256 + tid;
        if (j < NOUT) {
            const int cc   = j / NITEM;
            const int rest = j - cc * NITEM;
            const int o    = rest / NBIN;
            const int bin  = rest - o * NBIN;
            const int p0   = (o - ind + 8) & 7;
            const int p1   = (p0 + 1) & 7;
            ob[j] = 0.25f * (rv * acc[cc * NITEM + p0 * NBIN + bin]
                           + lv * acc[cc * NITEM + p1 * NBIN + bin]);
        }
    }
}

extern "C" void kernel_launch(void* const* d_in, const int* in_sizes, int n_in,
                              void* d_out, int out_size)
{
    const float* features = (const float*)d_in[0];
    const float* rois     = (const float*)d_in[1];
    float*       out      = (float*)d_out;

    const int R = in_sizes[1] / 6;
    dim3 grid((unsigned)R, 4);
    riroi_kernel<<<grid, 256>>>(features, rois, out);
}

// round 5
// speedup vs baseline: 2.9675x; 1.4731x over previous
#include <cuda_runtime.h>

// RiRoIAlign for GB300 — round-1 gather structure, channel-paired.
// features: (B=2, Ctot=256, H=256, W=256) fp32
// rois: (512, 6) fp32 = [batch, cx, cy, w, h, theta]
// out: (512, 256, 7, 7) fp32, channel = c*8 + o  (C=32, O=8)
//
// grid = (512 rois, 8 channel-groups of 4 channels). Each thread owns one
// (plane, bin) item and accumulates TWO channels at once (independent chains,
// geometry smem reads amortized 2x, L1 working set only 2x).

#define HH 256
#define WW 256
#define CT 256
#define OO 8
#define NBIN 49
#define NS 196
#define HW (HH * WW)
#define NITEM (OO * NBIN)        // 392
#define NCH 4                    // channels per CTA
#define NOUT (NCH * NITEM)       // 1568 floats, contiguous in out

__global__ __launch_bounds__(256, 5)
void riroi_kernel(const float* __restrict__ features,
                  const float* __restrict__ rois,
                  float* __restrict__ out)
{
    __shared__ int4   soff[NS];
    __shared__ float4 swt[NS];
    __shared__ float  acc[NOUT];

    const int r   = blockIdx.x;
    const int cg  = blockIdx.y;          // 8 groups of 4 channels
    const int tid = threadIdx.x;

    const float b_f = rois[r * 6 + 0];
    const float cwv = rois[r * 6 + 1] * 0.125f;
    const float chv = rois[r * 6 + 2] * 0.125f;
    const float rw  = fmaxf(rois[r * 6 + 3] * 0.125f, 1.0f);
    const float rh  = fmaxf(rois[r * 6 + 4] * 0.125f, 1.0f);
    const float th  = rois[r * 6 + 5];
    const int   b   = (int)b_f;

    const float st  = sinf(th);
    const float ctt = cosf(th);

    const float indf   = (th * 8.0f) / 6.283185307179586f;
    const float indflo = floorf(indf);
    const float lv     = indf - indflo;
    const float rv     = 1.0f - lv;
    int ind = (int)indflo;
    ind = ((ind % 8) + 8) % 8;

    const float bin_h = rh / 7.0f;
    const float bin_w = rw / 7.0f;

    // ---- per-sample geometry, order (py, gy, px, gx) ----
    if (tid < NS) {
        const int s  = tid;
        const int gx = s & 1;
        const int px = (s >> 1) % 7;
        const int gy = (s / 14) & 1;
        const int py = s / 28;

        const float yy = -rh * 0.5f + ((float)py + ((float)gy + 0.5f) * 0.5f) * bin_h;
        const float xx = -rw * 0.5f + ((float)px + ((float)gx + 0.5f) * 0.5f) * bin_w;

        const float x = xx * ctt - yy * st + cwv;
        const float y = xx * st + yy * ctt + chv;

        const bool valid = (y > -1.0f) && (y < 256.0f) && (x > -1.0f) && (x < 256.0f);

        const float yc = fmaxf(y, 0.0f);
        const float xc = fmaxf(x, 0.0f);
        int yl = (int)yc;
        int xl = (int)xc;
        int yh, xh;
        float yv, xv;
        if (yl >= HH - 1) { yl = HH - 1; yh = HH - 1; yv = (float)(HH - 1); }
        else              { yh = yl + 1;              yv = yc; }
        if (xl >= WW - 1) { xl = WW - 1; xh = WW - 1; xv = (float)(WW - 1); }
        else              { xh = xl + 1;              xv = xc; }

        const float ly = yv - (float)yl;
        const float lx = xv - (float)xl;
        const float hy = 1.0f - ly;
        const float hx = 1.0f - lx;
        const float vm = valid ? 1.0f : 0.0f;

        swt[s]  = make_float4(hy * hx * vm, hy * lx * vm, ly * hx * vm, ly * lx * vm);
        soff[s] = make_int4(yl * WW + xl, yl * WW + xh, yh * WW + xl, yh * WW + xh);
    }
    __syncthreads();

    // base: features[b, cg*NCH*8 + cc*8 + plane, :, :]
    const float* fb = features + ((size_t)b * CT + (size_t)cg * NCH * OO) * (size_t)HW;

    #pragma unroll 1
    for (int cp = 0; cp < NCH / 2; ++cp) {           // channel pairs
        const float* c0 = fb + (size_t)(cp * 2 + 0) * OO * HW;

        for (int it = tid; it < NITEM; it += 256) {
            const int plane = it / NBIN;
            const int bin   = it - plane * NBIN;
            const int py    = bin / 7;
            const int px    = bin - py * 7;
            const float* p0 = c0 + plane * HW;
            const float* p1 = p0 + OO * HW;          // second channel of pair

            float a0 = 0.0f, a1 = 0.0f;
            #pragma unroll
            for (int gy = 0; gy < 2; ++gy) {
                #pragma unroll
                for (int gx = 0; gx < 2; ++gx) {
                    const int s = ((py * 2 + gy) * 7 + px) * 2 + gx;
                    const int4   o = soff[s];
                    const float4 w = swt[s];
                    const float t00 = __ldg(p0 + o.x);
                    const float t01 = __ldg(p0 + o.y);
                    const float t02 = __ldg(p0 + o.z);
                    const float t03 = __ldg(p0 + o.w);
                    const float t10 = __ldg(p1 + o.x);
                    const float t11 = __ldg(p1 + o.y);
                    const float t12 = __ldg(p1 + o.z);
                    const float t13 = __ldg(p1 + o.w);
                    a0 += w.x * t00 + w.y * t01 + w.z * t02 + w.w * t03;
                    a1 += w.x * t10 + w.y * t11 + w.z * t12 + w.w * t13;
                }
            }
            acc[(cp * 2 + 0) * NITEM + it] = a0;
            acc[(cp * 2 + 1) * NITEM + it] = a1;
        }
    }
    __syncthreads();

    // out[r, cg*NCH*8 .. +NCH*8, 7, 7] is one contiguous NOUT-float run;
    // j = cc*392 + o*49 + bin == (cc*8+o)*49 + bin matches memory order.
    float* ob = out + ((size_t)r * CT + (size_t)cg * NCH * OO) * (size_t)NBIN;
    for (int j = tid; j < NOUT; j += 256) {
        const int cc   = j / NITEM;
        const int rest = j - cc * NITEM;
        const int o    = rest / NBIN;
        const int bin  = rest - o * NBIN;
        const int p0   = (o - ind + 8) & 7;
        const int p1   = (p0 + 1) & 7;
        ob[j] = 0.25f * (rv * acc[cc * NITEM + p0 * NBIN + bin]
                       + lv * acc[cc * NITEM + p1 * NBIN + bin]);
    }
}

extern "C" void kernel_launch(void* const* d_in, const int* in_sizes, int n_in,
                              void* d_out, int out_size)
{
    const float* features = (const float*)d_in[0];
    const float* rois     = (const float*)d_in[1];
    float*       out      = (float*)d_out;

    const int R = in_sizes[1] / 6;
    dim3 grid((unsigned)R, 8);
    riroi_kernel<<<grid, 256>>>(features, rois, out);
}